// round 4
// baseline (speedup 1.0000x reference)
#include <cuda_runtime.h>
#include <cuda_bf16.h>

#define NN 51200
#define EE 1638400
#define GG 512
#define HCc 128
#define SLOPE 0.2f
#define CHUNK 96

// ---------------- scratch (device globals; no allocation allowed) ----------------
__device__ float g_xl[NN * HCc];
__device__ float g_xr[NN * HCc];
__device__ float g_h [NN * HCc];
__device__ int   g_deg[NN];
__device__ int   g_rowptr[NN + 1];
__device__ int   g_cursor[NN];
__device__ int   g_csr_src[EE];
__device__ float g_pool[GG * HCc];
__device__ float g_m1[GG * HCc];
__device__ float g_m2[GG * HCc];

// ---------------- f32x2 packed helpers (sm_103a FFMA2) ----------------
__device__ __forceinline__ void ffma2(unsigned long long& d,
                                      unsigned long long a, unsigned long long b) {
    asm("fma.rn.f32x2 %0, %1, %2, %3;" : "=l"(d) : "l"(a), "l"(b), "l"(d));
}
__device__ __forceinline__ unsigned long long pack2(float v) {
    unsigned long long r;
    unsigned u = __float_as_uint(v);
    asm("mov.b64 %0, {%1, %1};" : "=l"(r) : "r"(u));
    return r;
}
__device__ __forceinline__ float lo2(unsigned long long v) { return __uint_as_float((unsigned)v); }
__device__ __forceinline__ float hi2(unsigned long long v) { return __uint_as_float((unsigned)(v >> 32)); }

// ---------------- CSR build ----------------
__global__ void zero_deg_kernel() {
    for (int i = blockIdx.x * blockDim.x + threadIdx.x; i < NN; i += gridDim.x * blockDim.x)
        g_deg[i] = 0;
}

__global__ void hist_kernel(const int* __restrict__ dst) {
    const int4* d4 = (const int4*)dst;
    for (int e = blockIdx.x * blockDim.x + threadIdx.x; e < EE / 4; e += gridDim.x * blockDim.x) {
        int4 v = d4[e];
        atomicAdd(&g_deg[v.x], 1);
        atomicAdd(&g_deg[v.y], 1);
        atomicAdd(&g_deg[v.z], 1);
        atomicAdd(&g_deg[v.w], 1);
    }
}

// single block, 1024 threads, 50 elems each (1024*50 == 51200)
__global__ void scan_kernel() {
    __shared__ int ss[1024];
    const int t = threadIdx.x;
    const int base = t * 50;
    int s = 0;
#pragma unroll 5
    for (int j = 0; j < 50; j++) s += g_deg[base + j];
    ss[t] = s;
    __syncthreads();
    for (int off = 1; off < 1024; off <<= 1) {
        int v = (t >= off) ? ss[t - off] : 0;
        __syncthreads();
        ss[t] += v;
        __syncthreads();
    }
    int run = (t > 0) ? ss[t - 1] : 0;
    for (int j = 0; j < 50; j++) {
        g_rowptr[base + j] = run;
        g_cursor[base + j] = run;
        run += g_deg[base + j];
    }
    if (t == 1023) g_rowptr[NN] = run;
}

__global__ void scatter_kernel(const int* __restrict__ src, const int* __restrict__ dst) {
    const int4* s4 = (const int4*)src;
    const int4* d4 = (const int4*)dst;
    for (int e = blockIdx.x * blockDim.x + threadIdx.x; e < EE / 4; e += gridDim.x * blockDim.x) {
        int4 sv = s4[e];
        int4 dv = d4[e];
        g_csr_src[atomicAdd(&g_cursor[dv.x], 1)] = sv.x;
        g_csr_src[atomicAdd(&g_cursor[dv.y], 1)] = sv.y;
        g_csr_src[atomicAdd(&g_cursor[dv.z], 1)] = sv.z;
        g_csr_src[atomicAdd(&g_cursor[dv.w], 1)] = sv.w;
    }
}

// ---------------- dual GEMM (FFMA2): xl = in@Wl + bl ; xr = in@Wr + br ----------------
template <int DIN>
__global__ __launch_bounds__(256) void dual_gemm_kernel(
                                 const float* __restrict__ in_param,
                                 const float* __restrict__ Wl, const float* __restrict__ bl,
                                 const float* __restrict__ Wr, const float* __restrict__ br) {
    constexpr int KT = (DIN < 32) ? DIN : 32;
    __shared__ __align__(16) float sW[KT * 264];   // [k][o], stride 264
    __shared__ __align__(16) float sIn[64 * 36];   // [node][k], stride 36

    const float* in = in_param ? in_param : g_h;
    const int tid  = threadIdx.x;
    const int part = tid & 15;
    const int ng   = tid >> 4;

    unsigned long long acc[4][4][2];   // [node][quad][pair]
#pragma unroll
    for (int j = 0; j < 4; j++)
#pragma unroll
        for (int c = 0; c < 4; c++) { acc[j][c][0] = 0ull; acc[j][c][1] = 0ull; }

    for (int kt = 0; kt < DIN; kt += KT) {
        for (int idx = tid; idx < KT * 256; idx += 256) {
            int k = idx >> 8;
            int o = idx & 255;
            float v = (o < 128) ? Wl[(kt + k) * 128 + o] : Wr[(kt + k) * 128 + (o - 128)];
            sW[k * 264 + o] = v;
        }
        for (int idx = tid; idx < 64 * KT; idx += 256) {
            int n = idx / KT;
            int k = idx - n * KT;
            sIn[n * 36 + k] = in[(blockIdx.x * 64 + n) * DIN + kt + k];
        }
        __syncthreads();

#pragma unroll
        for (int k = 0; k < KT; k += 4) {
            unsigned long long ivp[4][4];
#pragma unroll
            for (int j = 0; j < 4; j++) {
                float4 iv = *(const float4*)&sIn[(ng * 4 + j) * 36 + k];
                ivp[j][0] = pack2(iv.x); ivp[j][1] = pack2(iv.y);
                ivp[j][2] = pack2(iv.z); ivp[j][3] = pack2(iv.w);
            }
#pragma unroll
            for (int kk = 0; kk < 4; kk++) {
#pragma unroll
                for (int c = 0; c < 4; c++) {
                    double2 wv = *(const double2*)&sW[(k + kk) * 264 + part * 4 + c * 64];
                    unsigned long long w01 = __double_as_longlong(wv.x);
                    unsigned long long w23 = __double_as_longlong(wv.y);
#pragma unroll
                    for (int j = 0; j < 4; j++) {
                        ffma2(acc[j][c][0], ivp[j][kk], w01);
                        ffma2(acc[j][c][1], ivp[j][kk], w23);
                    }
                }
            }
        }
        __syncthreads();
    }

    const int gn0 = blockIdx.x * 64 + ng * 4;
#pragma unroll
    for (int j = 0; j < 4; j++) {
        const int row = (gn0 + j) * 128;
#pragma unroll
        for (int c = 0; c < 4; c++) {
            const int o = part * 4 + c * 64;
            float4 v;
            v.x = lo2(acc[j][c][0]); v.y = hi2(acc[j][c][0]);
            v.z = lo2(acc[j][c][1]); v.w = hi2(acc[j][c][1]);
            if (c < 2) {
                v.x += bl[o]; v.y += bl[o + 1]; v.z += bl[o + 2]; v.w += bl[o + 3];
                *(float4*)&g_xl[row + o] = v;
            } else {
                const int o2 = o - 128;
                v.x += br[o2]; v.y += br[o2 + 1]; v.z += br[o2 + 2]; v.w += br[o2 + 3];
                *(float4*)&g_xr[row + o2] = v;
            }
        }
    }
}

// ---------------- fused GATv2 aggregation (one warp per dst node) ----------------
// max-free segment softmax (scores bounded small by construction).
// CSR indices staged to smem (kills index->data L2 chain); data loads
// unconditional (clamped) and pipelined 8 edges ahead; 4 independent states.
__device__ __forceinline__ void edge_update(const float4 a, const float4 xr4, const float4 at4,
                                            float& d, float4& acc) {
    float tx = a.x + xr4.x; tx = fmaxf(tx, SLOPE * tx);
    float ty = a.y + xr4.y; ty = fmaxf(ty, SLOPE * ty);
    float tz = a.z + xr4.z; tz = fmaxf(tz, SLOPE * tz);
    float tw = a.w + xr4.w; tw = fmaxf(tw, SLOPE * tw);
    float p = tx * at4.x + ty * at4.y + tz * at4.z + tw * at4.w;
    p += __shfl_xor_sync(0xffffffffu, p, 1);
    p += __shfl_xor_sync(0xffffffffu, p, 2);
    p += __shfl_xor_sync(0xffffffffu, p, 4);   // per-head score (8-lane groups)
    float w = __expf(p);
    d += w;
    acc.x = fmaf(w, a.x, acc.x);
    acc.y = fmaf(w, a.y, acc.y);
    acc.z = fmaf(w, a.z, acc.z);
    acc.w = fmaf(w, a.w, acc.w);
}

__global__ __launch_bounds__(256) void gat_agg_kernel(const float* __restrict__ att,
                                                      const float* __restrict__ bias) {
    __shared__ int sidx[8][CHUNK];
    const int warp = threadIdx.x >> 5;
    const int lane = threadIdx.x & 31;
    const int node = blockIdx.x * 8 + warp;

    const float4 xr4 = *(const float4*)(g_xr + node * 128 + lane * 4);
    const float4 at4 = *(const float4*)(att + lane * 4);
    const float4 b4  = *(const float4*)(bias + lane * 4);

    const int beg = g_rowptr[node];
    const int end = g_rowptr[node + 1];

    float d0 = 0.f, d1 = 0.f, d2 = 0.f, d3 = 0.f;
    float4 acc0 = make_float4(0.f, 0.f, 0.f, 0.f);
    float4 acc1 = acc0, acc2 = acc0, acc3 = acc0;

    for (int cb = beg; cb < end; cb += CHUNK) {
        const int cnt = min(CHUNK, end - cb);
        // stage indices (coalesced)
        for (int i = lane; i < cnt; i += 32) sidx[warp][i] = g_csr_src[cb + i];
        __syncwarp();

        const int last = cnt - 1;
        // prime pipeline: r = edges 0..3, p = edges 4..7 (clamped)
        float4 r0 = *(const float4*)(g_xl + sidx[warp][0]             * 128 + lane * 4);
        float4 r1 = *(const float4*)(g_xl + sidx[warp][min(1, last)]  * 128 + lane * 4);
        float4 r2 = *(const float4*)(g_xl + sidx[warp][min(2, last)]  * 128 + lane * 4);
        float4 r3 = *(const float4*)(g_xl + sidx[warp][min(3, last)]  * 128 + lane * 4);
        float4 p0 = *(const float4*)(g_xl + sidx[warp][min(4, last)]  * 128 + lane * 4);
        float4 p1 = *(const float4*)(g_xl + sidx[warp][min(5, last)]  * 128 + lane * 4);
        float4 p2 = *(const float4*)(g_xl + sidx[warp][min(6, last)]  * 128 + lane * 4);
        float4 p3 = *(const float4*)(g_xl + sidx[warp][min(7, last)]  * 128 + lane * 4);

        int k = 0;
        for (; k + 4 <= cnt; k += 4) {
            float4 q0 = *(const float4*)(g_xl + sidx[warp][min(k +  8, last)] * 128 + lane * 4);
            float4 q1 = *(const float4*)(g_xl + sidx[warp][min(k +  9, last)] * 128 + lane * 4);
            float4 q2 = *(const float4*)(g_xl + sidx[warp][min(k + 10, last)] * 128 + lane * 4);
            float4 q3 = *(const float4*)(g_xl + sidx[warp][min(k + 11, last)] * 128 + lane * 4);
            edge_update(r0, xr4, at4, d0, acc0);
            edge_update(r1, xr4, at4, d1, acc1);
            edge_update(r2, xr4, at4, d2, acc2);
            edge_update(r3, xr4, at4, d3, acc3);
            r0 = p0; r1 = p1; r2 = p2; r3 = p3;
            p0 = q0; p1 = q1; p2 = q2; p3 = q3;
        }
        // tail (<4 edges, already loaded in r)
        if (k     < cnt) edge_update(r0, xr4, at4, d0, acc0);
        if (k + 1 < cnt) edge_update(r1, xr4, at4, d1, acc1);
        if (k + 2 < cnt) edge_update(r2, xr4, at4, d2, acc2);
        __syncwarp();
    }

    float dsum = (d0 + d1) + (d2 + d3);
    float4 acc;
    acc.x = (acc0.x + acc1.x) + (acc2.x + acc3.x);
    acc.y = (acc0.y + acc1.y) + (acc2.y + acc3.y);
    acc.z = (acc0.z + acc1.z) + (acc2.z + acc3.z);
    acc.w = (acc0.w + acc1.w) + (acc2.w + acc3.w);

    float inv = 1.f / (dsum + 1e-16f);
    float4 o;
    o.x = fmaxf(fmaf(acc.x, inv, b4.x), 0.f);
    o.y = fmaxf(fmaf(acc.y, inv, b4.y), 0.f);
    o.z = fmaxf(fmaf(acc.z, inv, b4.z), 0.f);
    o.w = fmaxf(fmaf(acc.w, inv, b4.w), 0.f);
    *(float4*)(g_h + node * 128 + lane * 4) = o;
}

// ---------------- global mean pool (batch is sorted) ----------------
__global__ void pool_kernel(const int* __restrict__ batch) {
    const int g = blockIdx.x;
    const int t = threadIdx.x;  // 128 threads
    __shared__ int sb, se;
    if (t == 0) {
        int lo = 0, hi = NN;
        while (lo < hi) { int mid = (lo + hi) >> 1; if (batch[mid] < g) lo = mid + 1; else hi = mid; }
        sb = lo;
        hi = NN;
        while (lo < hi) { int mid = (lo + hi) >> 1; if (batch[mid] < g + 1) lo = mid + 1; else hi = mid; }
        se = lo;
    }
    __syncthreads();
    float s0 = 0.f, s1 = 0.f, s2 = 0.f, s3 = 0.f;
    int n = sb;
    for (; n + 4 <= se; n += 4) {
        s0 += g_h[(n + 0) * 128 + t];
        s1 += g_h[(n + 1) * 128 + t];
        s2 += g_h[(n + 2) * 128 + t];
        s3 += g_h[(n + 3) * 128 + t];
    }
    for (; n < se; n++) s0 += g_h[n * 128 + t];
    float s = (s0 + s1) + (s2 + s3);
    int cnt = se - sb;
    g_pool[g * 128 + t] = s / (float)(cnt > 0 ? cnt : 1);
}

// ---------------- MLP head ----------------
__global__ void fc_bn_relu_kernel(int stage,
                                  const float* __restrict__ W, const float* __restrict__ b,
                                  const float* __restrict__ gamma, const float* __restrict__ beta) {
    const float* in = (stage == 0) ? g_pool : g_m1;
    float* out      = (stage == 0) ? g_m1   : g_m2;
    const int g = blockIdx.x, t = threadIdx.x;
    __shared__ float sin[128];
    sin[t] = in[g * 128 + t];
    __syncthreads();
    float a0 = b[t], a1 = 0.f;
#pragma unroll 4
    for (int k = 0; k < 128; k += 2) {
        a0 = fmaf(sin[k],     W[(k)     * 128 + t], a0);
        a1 = fmaf(sin[k + 1], W[(k + 1) * 128 + t], a1);
    }
    float a = a0 + a1;
    float scale = gamma[t] * rsqrtf(1.0f + 1e-5f);
    a = fmaxf(fmaf(a, scale, beta[t]), 0.f);
    out[g * 128 + t] = a;
}

__global__ void fc3_kernel(const float* __restrict__ W, const float* __restrict__ b,
                           float* __restrict__ out) {
    const int g = blockIdx.x, t = threadIdx.x;  // 128 threads
    __shared__ float sin[128];
    __shared__ float w0[4], w1[4];
    sin[t] = g_m2[g * 128 + t];
    __syncthreads();
    float p0 = sin[t] * W[t * 2 + 0];
    float p1 = sin[t] * W[t * 2 + 1];
#pragma unroll
    for (int off = 16; off; off >>= 1) {
        p0 += __shfl_xor_sync(0xffffffffu, p0, off);
        p1 += __shfl_xor_sync(0xffffffffu, p1, off);
    }
    if ((t & 31) == 0) { w0[t >> 5] = p0; w1[t >> 5] = p1; }
    __syncthreads();
    if (t == 0) out[g * 2 + 0] = w0[0] + w0[1] + w0[2] + w0[3] + b[0];
    if (t == 1) out[g * 2 + 1] = w1[0] + w1[1] + w1[2] + w1[3] + b[1];
}

// ---------------- launch ----------------
extern "C" void kernel_launch(void* const* d_in, const int* in_sizes, int n_in,
                              void* d_out, int out_size) {
    const float* x      = (const float*)d_in[0];
    const int*   ei     = (const int*)  d_in[1];
    const int*   batch  = (const int*)  d_in[2];
    const float* l1_Wl  = (const float*)d_in[3];
    const float* l1_bl  = (const float*)d_in[4];
    const float* l1_Wr  = (const float*)d_in[5];
    const float* l1_br  = (const float*)d_in[6];
    const float* l1_att = (const float*)d_in[7];
    const float* l1_bias= (const float*)d_in[8];
    const float* l2_Wl  = (const float*)d_in[9];
    const float* l2_bl  = (const float*)d_in[10];
    const float* l2_Wr  = (const float*)d_in[11];
    const float* l2_br  = (const float*)d_in[12];
    const float* l2_att = (const float*)d_in[13];
    const float* l2_bias= (const float*)d_in[14];
    const float* fc1_W  = (const float*)d_in[15];
    const float* fc1_b  = (const float*)d_in[16];
    const float* bn1_g  = (const float*)d_in[17];
    const float* bn1_b  = (const float*)d_in[18];
    const float* fc2_W  = (const float*)d_in[19];
    const float* fc2_b  = (const float*)d_in[20];
    const float* bn2_g  = (const float*)d_in[21];
    const float* bn2_b  = (const float*)d_in[22];
    const float* fc3_W  = (const float*)d_in[23];
    const float* fc3_b  = (const float*)d_in[24];

    const int* src = ei;
    const int* dst = ei + EE;
    float* out = (float*)d_out;

    // CSR by destination (shared by both layers)
    zero_deg_kernel<<<200, 256>>>();
    hist_kernel<<<1600, 256>>>(dst);
    scan_kernel<<<1, 1024>>>();
    scatter_kernel<<<1600, 256>>>(src, dst);

    // Layer 1
    dual_gemm_kernel<16><<<NN / 64, 256>>>(x, l1_Wl, l1_bl, l1_Wr, l1_br);
    gat_agg_kernel<<<NN / 8, 256>>>(l1_att, l1_bias);

    // Layer 2
    dual_gemm_kernel<128><<<NN / 64, 256>>>(nullptr, l2_Wl, l2_bl, l2_Wr, l2_br);
    gat_agg_kernel<<<NN / 8, 256>>>(l2_att, l2_bias);

    // Pool + MLP head
    pool_kernel<<<GG, 128>>>(batch);
    fc_bn_relu_kernel<<<GG, 128>>>(0, fc1_W, fc1_b, bn1_g, bn1_b);
    fc_bn_relu_kernel<<<GG, 128>>>(1, fc2_W, fc2_b, bn2_g, bn2_b);
    fc3_kernel<<<GG, 128>>>(fc3_W, fc3_b, out);
}

// round 5
// speedup vs baseline: 1.1452x; 1.1452x over previous
#include <cuda_runtime.h>
#include <cuda_bf16.h>

#define NN 51200
#define EE 1638400
#define GG 512
#define HCc 128
#define SLOPE 0.2f
#define CHUNK 96

// ---------------- scratch (device globals; no allocation allowed) ----------------
__device__ float g_xl[NN * HCc];
__device__ float g_xr[NN * HCc];
__device__ float g_h [NN * HCc];
__device__ int   g_deg[NN];
__device__ int   g_rowptr[NN + 1];
__device__ int   g_cursor[NN];
__device__ int   g_csr_src[EE];
__device__ float g_pool[GG * HCc];
__device__ float g_m1[GG * HCc];
__device__ float g_m2[GG * HCc];

// ---------------- f32x2 packed helpers (sm_103a FFMA2) ----------------
__device__ __forceinline__ void ffma2(unsigned long long& d,
                                      unsigned long long a, unsigned long long b) {
    asm("fma.rn.f32x2 %0, %1, %2, %3;" : "=l"(d) : "l"(a), "l"(b), "l"(d));
}
__device__ __forceinline__ unsigned long long pack2(float v) {
    unsigned long long r;
    unsigned u = __float_as_uint(v);
    asm("mov.b64 %0, {%1, %1};" : "=l"(r) : "r"(u));
    return r;
}
__device__ __forceinline__ float lo2(unsigned long long v) { return __uint_as_float((unsigned)v); }
__device__ __forceinline__ float hi2(unsigned long long v) { return __uint_as_float((unsigned)(v >> 32)); }

// ---------------- CSR build ----------------
__global__ void zero_deg_kernel() {
    for (int i = blockIdx.x * blockDim.x + threadIdx.x; i < NN; i += gridDim.x * blockDim.x)
        g_deg[i] = 0;
}

__global__ void hist_kernel(const int* __restrict__ dst) {
    const int4* d4 = (const int4*)dst;
    for (int e = blockIdx.x * blockDim.x + threadIdx.x; e < EE / 4; e += gridDim.x * blockDim.x) {
        int4 v = d4[e];
        atomicAdd(&g_deg[v.x], 1);
        atomicAdd(&g_deg[v.y], 1);
        atomicAdd(&g_deg[v.z], 1);
        atomicAdd(&g_deg[v.w], 1);
    }
}

// single block, 1024 threads, 50 elems each (1024*50 == 51200)
__global__ void scan_kernel() {
    __shared__ int ss[1024];
    const int t = threadIdx.x;
    const int base = t * 50;
    int s = 0;
#pragma unroll 5
    for (int j = 0; j < 50; j++) s += g_deg[base + j];
    ss[t] = s;
    __syncthreads();
    for (int off = 1; off < 1024; off <<= 1) {
        int v = (t >= off) ? ss[t - off] : 0;
        __syncthreads();
        ss[t] += v;
        __syncthreads();
    }
    int run = (t > 0) ? ss[t - 1] : 0;
    for (int j = 0; j < 50; j++) {
        g_rowptr[base + j] = run;
        g_cursor[base + j] = run;
        run += g_deg[base + j];
    }
    if (t == 1023) g_rowptr[NN] = run;
}

__global__ void scatter_kernel(const int* __restrict__ src, const int* __restrict__ dst) {
    const int4* s4 = (const int4*)src;
    const int4* d4 = (const int4*)dst;
    for (int e = blockIdx.x * blockDim.x + threadIdx.x; e < EE / 4; e += gridDim.x * blockDim.x) {
        int4 sv = s4[e];
        int4 dv = d4[e];
        g_csr_src[atomicAdd(&g_cursor[dv.x], 1)] = sv.x;
        g_csr_src[atomicAdd(&g_cursor[dv.y], 1)] = sv.y;
        g_csr_src[atomicAdd(&g_cursor[dv.z], 1)] = sv.z;
        g_csr_src[atomicAdd(&g_cursor[dv.w], 1)] = sv.w;
    }
}

// ---------------- dual GEMM (FFMA2): xl = in@Wl + bl ; xr = in@Wr + br ----------------
template <int DIN>
__global__ __launch_bounds__(256) void dual_gemm_kernel(
                                 const float* __restrict__ in_param,
                                 const float* __restrict__ Wl, const float* __restrict__ bl,
                                 const float* __restrict__ Wr, const float* __restrict__ br) {
    constexpr int KT = (DIN < 32) ? DIN : 32;
    __shared__ __align__(16) float sW[KT * 264];   // [k][o], stride 264
    __shared__ __align__(16) float sIn[64 * 36];   // [node][k], stride 36

    const float* in = in_param ? in_param : g_h;
    const int tid  = threadIdx.x;
    const int part = tid & 15;
    const int ng   = tid >> 4;

    unsigned long long acc[4][4][2];   // [node][quad][pair]
#pragma unroll
    for (int j = 0; j < 4; j++)
#pragma unroll
        for (int c = 0; c < 4; c++) { acc[j][c][0] = 0ull; acc[j][c][1] = 0ull; }

    for (int kt = 0; kt < DIN; kt += KT) {
        for (int idx = tid; idx < KT * 256; idx += 256) {
            int k = idx >> 8;
            int o = idx & 255;
            float v = (o < 128) ? Wl[(kt + k) * 128 + o] : Wr[(kt + k) * 128 + (o - 128)];
            sW[k * 264 + o] = v;
        }
        for (int idx = tid; idx < 64 * KT; idx += 256) {
            int n = idx / KT;
            int k = idx - n * KT;
            sIn[n * 36 + k] = in[(blockIdx.x * 64 + n) * DIN + kt + k];
        }
        __syncthreads();

#pragma unroll
        for (int k = 0; k < KT; k += 4) {
            unsigned long long ivp[4][4];
#pragma unroll
            for (int j = 0; j < 4; j++) {
                float4 iv = *(const float4*)&sIn[(ng * 4 + j) * 36 + k];
                ivp[j][0] = pack2(iv.x); ivp[j][1] = pack2(iv.y);
                ivp[j][2] = pack2(iv.z); ivp[j][3] = pack2(iv.w);
            }
#pragma unroll
            for (int kk = 0; kk < 4; kk++) {
#pragma unroll
                for (int c = 0; c < 4; c++) {
                    double2 wv = *(const double2*)&sW[(k + kk) * 264 + part * 4 + c * 64];
                    unsigned long long w01 = __double_as_longlong(wv.x);
                    unsigned long long w23 = __double_as_longlong(wv.y);
#pragma unroll
                    for (int j = 0; j < 4; j++) {
                        ffma2(acc[j][c][0], ivp[j][kk], w01);
                        ffma2(acc[j][c][1], ivp[j][kk], w23);
                    }
                }
            }
        }
        __syncthreads();
    }

    const int gn0 = blockIdx.x * 64 + ng * 4;
#pragma unroll
    for (int j = 0; j < 4; j++) {
        const int row = (gn0 + j) * 128;
#pragma unroll
        for (int c = 0; c < 4; c++) {
            const int o = part * 4 + c * 64;
            float4 v;
            v.x = lo2(acc[j][c][0]); v.y = hi2(acc[j][c][0]);
            v.z = lo2(acc[j][c][1]); v.w = hi2(acc[j][c][1]);
            if (c < 2) {
                v.x += bl[o]; v.y += bl[o + 1]; v.z += bl[o + 2]; v.w += bl[o + 3];
                *(float4*)&g_xl[row + o] = v;
            } else {
                const int o2 = o - 128;
                v.x += br[o2]; v.y += br[o2 + 1]; v.z += br[o2 + 2]; v.w += br[o2 + 3];
                *(float4*)&g_xr[row + o2] = v;
            }
        }
    }
}

// ---------------- fused GATv2 aggregation (one warp per dst node) ----------------
// max-free segment softmax. Indices staged in smem (LDS, no index->data L2
// chain). 8-row register pipeline, EXACT conditional loads (no over-fetch),
// prefetch issued 8 edges ahead of use. 4 independent accumulation states.
__device__ __forceinline__ void edge_update(const float4 a, const float4 xr4, const float4 at4,
                                            float& d, float4& acc) {
    float tx = a.x + xr4.x; tx = fmaxf(tx, SLOPE * tx);
    float ty = a.y + xr4.y; ty = fmaxf(ty, SLOPE * ty);
    float tz = a.z + xr4.z; tz = fmaxf(tz, SLOPE * tz);
    float tw = a.w + xr4.w; tw = fmaxf(tw, SLOPE * tw);
    float p = tx * at4.x + ty * at4.y + tz * at4.z + tw * at4.w;
    p += __shfl_xor_sync(0xffffffffu, p, 1);
    p += __shfl_xor_sync(0xffffffffu, p, 2);
    p += __shfl_xor_sync(0xffffffffu, p, 4);   // per-head score (8-lane groups)
    float w = __expf(p);
    d += w;
    acc.x = fmaf(w, a.x, acc.x);
    acc.y = fmaf(w, a.y, acc.y);
    acc.z = fmaf(w, a.z, acc.z);
    acc.w = fmaf(w, a.w, acc.w);
}

__global__ __launch_bounds__(256) void gat_agg_kernel(const float* __restrict__ att,
                                                      const float* __restrict__ bias) {
    __shared__ int sidx[8][CHUNK];
    const int warp = threadIdx.x >> 5;
    const int lane = threadIdx.x & 31;
    const int node = blockIdx.x * 8 + warp;

    const float4 xr4 = *(const float4*)(g_xr + node * 128 + lane * 4);
    const float4 at4 = *(const float4*)(att + lane * 4);
    const float4 b4  = *(const float4*)(bias + lane * 4);

    const int beg = g_rowptr[node];
    const int end = g_rowptr[node + 1];

    float d0 = 0.f, d1 = 0.f, d2 = 0.f, d3 = 0.f;
    float4 acc0 = make_float4(0.f, 0.f, 0.f, 0.f);
    float4 acc1 = acc0, acc2 = acc0, acc3 = acc0;

    for (int cb = beg; cb < end; cb += CHUNK) {
        const int cnt = min(CHUNK, end - cb);
        for (int i = lane; i < cnt; i += 32) sidx[warp][i] = g_csr_src[cb + i];
        __syncwarp();

        // 8-row register pipeline; invariant: b_i holds edge (k+i) when k+i < cnt
        float4 b0, b1, b2, b3, b4r, b5, b6, b7;
        if (0 < cnt) b0  = *(const float4*)(g_xl + sidx[warp][0] * 128 + lane * 4);
        if (1 < cnt) b1  = *(const float4*)(g_xl + sidx[warp][1] * 128 + lane * 4);
        if (2 < cnt) b2  = *(const float4*)(g_xl + sidx[warp][2] * 128 + lane * 4);
        if (3 < cnt) b3  = *(const float4*)(g_xl + sidx[warp][3] * 128 + lane * 4);
        if (4 < cnt) b4r = *(const float4*)(g_xl + sidx[warp][4] * 128 + lane * 4);
        if (5 < cnt) b5  = *(const float4*)(g_xl + sidx[warp][5] * 128 + lane * 4);
        if (6 < cnt) b6  = *(const float4*)(g_xl + sidx[warp][6] * 128 + lane * 4);
        if (7 < cnt) b7  = *(const float4*)(g_xl + sidx[warp][7] * 128 + lane * 4);

        int k = 0;
        for (; k + 4 <= cnt; k += 4) {
            float4 t0, t1, t2, t3;
            if (k +  8 < cnt) t0 = *(const float4*)(g_xl + sidx[warp][k +  8] * 128 + lane * 4);
            if (k +  9 < cnt) t1 = *(const float4*)(g_xl + sidx[warp][k +  9] * 128 + lane * 4);
            if (k + 10 < cnt) t2 = *(const float4*)(g_xl + sidx[warp][k + 10] * 128 + lane * 4);
            if (k + 11 < cnt) t3 = *(const float4*)(g_xl + sidx[warp][k + 11] * 128 + lane * 4);
            edge_update(b0, xr4, at4, d0, acc0);
            edge_update(b1, xr4, at4, d1, acc1);
            edge_update(b2, xr4, at4, d2, acc2);
            edge_update(b3, xr4, at4, d3, acc3);
            b0 = b4r; b1 = b5; b2 = b6; b3 = b7;
            b4r = t0; b5 = t1; b6 = t2; b7 = t3;
        }
        if (k     < cnt) edge_update(b0, xr4, at4, d0, acc0);
        if (k + 1 < cnt) edge_update(b1, xr4, at4, d1, acc1);
        if (k + 2 < cnt) edge_update(b2, xr4, at4, d2, acc2);
        __syncwarp();
    }

    float dsum = (d0 + d1) + (d2 + d3);
    float4 acc;
    acc.x = (acc0.x + acc1.x) + (acc2.x + acc3.x);
    acc.y = (acc0.y + acc1.y) + (acc2.y + acc3.y);
    acc.z = (acc0.z + acc1.z) + (acc2.z + acc3.z);
    acc.w = (acc0.w + acc1.w) + (acc2.w + acc3.w);

    float inv = 1.f / (dsum + 1e-16f);
    float4 o;
    o.x = fmaxf(fmaf(acc.x, inv, b4.x), 0.f);
    o.y = fmaxf(fmaf(acc.y, inv, b4.y), 0.f);
    o.z = fmaxf(fmaf(acc.z, inv, b4.z), 0.f);
    o.w = fmaxf(fmaf(acc.w, inv, b4.w), 0.f);
    *(float4*)(g_h + node * 128 + lane * 4) = o;
}

// ---------------- global mean pool (batch is sorted) ----------------
__global__ void pool_kernel(const int* __restrict__ batch) {
    const int g = blockIdx.x;
    const int t = threadIdx.x;  // 128 threads
    __shared__ int sb, se;
    if (t == 0) {
        int lo = 0, hi = NN;
        while (lo < hi) { int mid = (lo + hi) >> 1; if (batch[mid] < g) lo = mid + 1; else hi = mid; }
        sb = lo;
        hi = NN;
        while (lo < hi) { int mid = (lo + hi) >> 1; if (batch[mid] < g + 1) lo = mid + 1; else hi = mid; }
        se = lo;
    }
    __syncthreads();
    float s0 = 0.f, s1 = 0.f, s2 = 0.f, s3 = 0.f;
    int n = sb;
    for (; n + 4 <= se; n += 4) {
        s0 += g_h[(n + 0) * 128 + t];
        s1 += g_h[(n + 1) * 128 + t];
        s2 += g_h[(n + 2) * 128 + t];
        s3 += g_h[(n + 3) * 128 + t];
    }
    for (; n < se; n++) s0 += g_h[n * 128 + t];
    float s = (s0 + s1) + (s2 + s3);
    int cnt = se - sb;
    g_pool[g * 128 + t] = s / (float)(cnt > 0 ? cnt : 1);
}

// ---------------- MLP head ----------------
__global__ void fc_bn_relu_kernel(int stage,
                                  const float* __restrict__ W, const float* __restrict__ b,
                                  const float* __restrict__ gamma, const float* __restrict__ beta) {
    const float* in = (stage == 0) ? g_pool : g_m1;
    float* out      = (stage == 0) ? g_m1   : g_m2;
    const int g = blockIdx.x, t = threadIdx.x;
    __shared__ float sin[128];
    sin[t] = in[g * 128 + t];
    __syncthreads();
    float a0 = b[t], a1 = 0.f;
#pragma unroll 4
    for (int k = 0; k < 128; k += 2) {
        a0 = fmaf(sin[k],     W[(k)     * 128 + t], a0);
        a1 = fmaf(sin[k + 1], W[(k + 1) * 128 + t], a1);
    }
    float a = a0 + a1;
    float scale = gamma[t] * rsqrtf(1.0f + 1e-5f);
    a = fmaxf(fmaf(a, scale, beta[t]), 0.f);
    out[g * 128 + t] = a;
}

__global__ void fc3_kernel(const float* __restrict__ W, const float* __restrict__ b,
                           float* __restrict__ out) {
    const int g = blockIdx.x, t = threadIdx.x;  // 128 threads
    __shared__ float sin[128];
    __shared__ float w0[4], w1[4];
    sin[t] = g_m2[g * 128 + t];
    __syncthreads();
    float p0 = sin[t] * W[t * 2 + 0];
    float p1 = sin[t] * W[t * 2 + 1];
#pragma unroll
    for (int off = 16; off; off >>= 1) {
        p0 += __shfl_xor_sync(0xffffffffu, p0, off);
        p1 += __shfl_xor_sync(0xffffffffu, p1, off);
    }
    if ((t & 31) == 0) { w0[t >> 5] = p0; w1[t >> 5] = p1; }
    __syncthreads();
    if (t == 0) out[g * 2 + 0] = w0[0] + w0[1] + w0[2] + w0[3] + b[0];
    if (t == 1) out[g * 2 + 1] = w1[0] + w1[1] + w1[2] + w1[3] + b[1];
}

// ---------------- launch ----------------
extern "C" void kernel_launch(void* const* d_in, const int* in_sizes, int n_in,
                              void* d_out, int out_size) {
    const float* x      = (const float*)d_in[0];
    const int*   ei     = (const int*)  d_in[1];
    const int*   batch  = (const int*)  d_in[2];
    const float* l1_Wl  = (const float*)d_in[3];
    const float* l1_bl  = (const float*)d_in[4];
    const float* l1_Wr  = (const float*)d_in[5];
    const float* l1_br  = (const float*)d_in[6];
    const float* l1_att = (const float*)d_in[7];
    const float* l1_bias= (const float*)d_in[8];
    const float* l2_Wl  = (const float*)d_in[9];
    const float* l2_bl  = (const float*)d_in[10];
    const float* l2_Wr  = (const float*)d_in[11];
    const float* l2_br  = (const float*)d_in[12];
    const float* l2_att = (const float*)d_in[13];
    const float* l2_bias= (const float*)d_in[14];
    const float* fc1_W  = (const float*)d_in[15];
    const float* fc1_b  = (const float*)d_in[16];
    const float* bn1_g  = (const float*)d_in[17];
    const float* bn1_b  = (const float*)d_in[18];
    const float* fc2_W  = (const float*)d_in[19];
    const float* fc2_b  = (const float*)d_in[20];
    const float* bn2_g  = (const float*)d_in[21];
    const float* bn2_b  = (const float*)d_in[22];
    const float* fc3_W  = (const float*)d_in[23];
    const float* fc3_b  = (const float*)d_in[24];

    const int* src = ei;
    const int* dst = ei + EE;
    float* out = (float*)d_out;

    // CSR by destination (shared by both layers)
    zero_deg_kernel<<<200, 256>>>();
    hist_kernel<<<1600, 256>>>(dst);
    scan_kernel<<<1, 1024>>>();
    scatter_kernel<<<1600, 256>>>(src, dst);

    // Layer 1
    dual_gemm_kernel<16><<<NN / 64, 256>>>(x, l1_Wl, l1_bl, l1_Wr, l1_br);
    gat_agg_kernel<<<NN / 8, 256>>>(l1_att, l1_bias);

    // Layer 2
    dual_gemm_kernel<128><<<NN / 64, 256>>>(nullptr, l2_Wl, l2_bl, l2_Wr, l2_br);
    gat_agg_kernel<<<NN / 8, 256>>>(l2_att, l2_bias);

    // Pool + MLP head
    pool_kernel<<<GG, 128>>>(batch);
    fc_bn_relu_kernel<<<GG, 128>>>(0, fc1_W, fc1_b, bn1_g, bn1_b);
    fc_bn_relu_kernel<<<GG, 128>>>(1, fc2_W, fc2_b, bn2_g, bn2_b);
    fc3_kernel<<<GG, 128>>>(fc3_W, fc3_b, out);
}

// round 7
// speedup vs baseline: 1.2720x; 1.1107x over previous
#include <cuda_runtime.h>
#include <cuda_fp16.h>
#include <cuda_bf16.h>

#define NN 51200
#define EE 1638400
#define GG 512
#define HCc 128
#define SLOPE 0.2f

// ---------------- scratch (device globals; no allocation allowed) ----------------
__device__ __half2 g_xlh[NN * 64];       // xl in fp16, 64 half2 per node row
__device__ float   g_xr[NN * HCc];
__device__ float   g_h [NN * HCc];
__device__ int     g_deg[NN];
__device__ int     g_rowptr[NN + 1];
__device__ int     g_cursor[NN];
__device__ int     g_csr_src[EE];
__device__ float   g_pool[GG * HCc];
__device__ float   g_m1[GG * HCc];
__device__ float   g_m2[GG * HCc];

// ---------------- f32x2 packed helpers (sm_103a FFMA2) ----------------
__device__ __forceinline__ void ffma2(unsigned long long& d,
                                      unsigned long long a, unsigned long long b) {
    asm("fma.rn.f32x2 %0, %1, %2, %3;" : "=l"(d) : "l"(a), "l"(b), "l"(d));
}
__device__ __forceinline__ unsigned long long pack2(float v) {
    unsigned long long r;
    unsigned u = __float_as_uint(v);
    asm("mov.b64 %0, {%1, %1};" : "=l"(r) : "r"(u));
    return r;
}
__device__ __forceinline__ float lo2(unsigned long long v) { return __uint_as_float((unsigned)v); }
__device__ __forceinline__ float hi2(unsigned long long v) { return __uint_as_float((unsigned)(v >> 32)); }

__device__ __forceinline__ unsigned h2_bits(__half2 h) {
    __half2_raw r = *(__half2_raw*)&h;
    return ((unsigned)r.y << 16) | (unsigned)r.x;
}

// ---------------- CSR build ----------------
__global__ void zero_deg_kernel() {
    for (int i = blockIdx.x * blockDim.x + threadIdx.x; i < NN; i += gridDim.x * blockDim.x)
        g_deg[i] = 0;
}

__global__ void hist_kernel(const int* __restrict__ dst) {
    const int4* d4 = (const int4*)dst;
    for (int e = blockIdx.x * blockDim.x + threadIdx.x; e < EE / 4; e += gridDim.x * blockDim.x) {
        int4 v = d4[e];
        atomicAdd(&g_deg[v.x], 1);
        atomicAdd(&g_deg[v.y], 1);
        atomicAdd(&g_deg[v.z], 1);
        atomicAdd(&g_deg[v.w], 1);
    }
}

// single block, 1024 threads, 50 elems each (1024*50 == 51200)
__global__ void scan_kernel() {
    __shared__ int ss[1024];
    const int t = threadIdx.x;
    const int base = t * 50;
    int s = 0;
#pragma unroll 5
    for (int j = 0; j < 50; j++) s += g_deg[base + j];
    ss[t] = s;
    __syncthreads();
    for (int off = 1; off < 1024; off <<= 1) {
        int v = (t >= off) ? ss[t - off] : 0;
        __syncthreads();
        ss[t] += v;
        __syncthreads();
    }
    int run = (t > 0) ? ss[t - 1] : 0;
    for (int j = 0; j < 50; j++) {
        g_rowptr[base + j] = run;
        g_cursor[base + j] = run;
        run += g_deg[base + j];
    }
    if (t == 1023) g_rowptr[NN] = run;
}

__global__ void scatter_kernel(const int* __restrict__ src, const int* __restrict__ dst) {
    const int4* s4 = (const int4*)src;
    const int4* d4 = (const int4*)dst;
    for (int e = blockIdx.x * blockDim.x + threadIdx.x; e < EE / 4; e += gridDim.x * blockDim.x) {
        int4 sv = s4[e];
        int4 dv = d4[e];
        g_csr_src[atomicAdd(&g_cursor[dv.x], 1)] = sv.x;
        g_csr_src[atomicAdd(&g_cursor[dv.y], 1)] = sv.y;
        g_csr_src[atomicAdd(&g_cursor[dv.z], 1)] = sv.z;
        g_csr_src[atomicAdd(&g_cursor[dv.w], 1)] = sv.w;
    }
}

// ---------------- dual GEMM (FFMA2): xl(fp16) = in@Wl + bl ; xr = in@Wr + br ----------------
template <int DIN>
__global__ __launch_bounds__(256) void dual_gemm_kernel(
                                 const float* __restrict__ in_param,
                                 const float* __restrict__ Wl, const float* __restrict__ bl,
                                 const float* __restrict__ Wr, const float* __restrict__ br) {
    constexpr int KT = (DIN < 32) ? DIN : 32;
    __shared__ __align__(16) float sW[KT * 264];   // [k][o], stride 264
    __shared__ __align__(16) float sIn[64 * 36];   // [node][k], stride 36

    const float* in = in_param ? in_param : g_h;
    const int tid  = threadIdx.x;
    const int part = tid & 15;
    const int ng   = tid >> 4;

    unsigned long long acc[4][4][2];   // [node][quad][pair]
#pragma unroll
    for (int j = 0; j < 4; j++)
#pragma unroll
        for (int c = 0; c < 4; c++) { acc[j][c][0] = 0ull; acc[j][c][1] = 0ull; }

    for (int kt = 0; kt < DIN; kt += KT) {
        for (int idx = tid; idx < KT * 256; idx += 256) {
            int k = idx >> 8;
            int o = idx & 255;
            float v = (o < 128) ? Wl[(kt + k) * 128 + o] : Wr[(kt + k) * 128 + (o - 128)];
            sW[k * 264 + o] = v;
        }
        for (int idx = tid; idx < 64 * KT; idx += 256) {
            int n = idx / KT;
            int k = idx - n * KT;
            sIn[n * 36 + k] = in[(blockIdx.x * 64 + n) * DIN + kt + k];
        }
        __syncthreads();

#pragma unroll
        for (int k = 0; k < KT; k += 4) {
            unsigned long long ivp[4][4];
#pragma unroll
            for (int j = 0; j < 4; j++) {
                float4 iv = *(const float4*)&sIn[(ng * 4 + j) * 36 + k];
                ivp[j][0] = pack2(iv.x); ivp[j][1] = pack2(iv.y);
                ivp[j][2] = pack2(iv.z); ivp[j][3] = pack2(iv.w);
            }
#pragma unroll
            for (int kk = 0; kk < 4; kk++) {
#pragma unroll
                for (int c = 0; c < 4; c++) {
                    double2 wv = *(const double2*)&sW[(k + kk) * 264 + part * 4 + c * 64];
                    unsigned long long w01 = __double_as_longlong(wv.x);
                    unsigned long long w23 = __double_as_longlong(wv.y);
#pragma unroll
                    for (int j = 0; j < 4; j++) {
                        ffma2(acc[j][c][0], ivp[j][kk], w01);
                        ffma2(acc[j][c][1], ivp[j][kk], w23);
                    }
                }
            }
        }
        __syncthreads();
    }

    const int gn0 = blockIdx.x * 64 + ng * 4;
#pragma unroll
    for (int j = 0; j < 4; j++) {
        const int node = gn0 + j;
#pragma unroll
        for (int c = 0; c < 4; c++) {
            const int o = part * 4 + c * 64;
            float4 v;
            v.x = lo2(acc[j][c][0]); v.y = hi2(acc[j][c][0]);
            v.z = lo2(acc[j][c][1]); v.w = hi2(acc[j][c][1]);
            if (c < 2) {
                v.x += bl[o]; v.y += bl[o + 1]; v.z += bl[o + 2]; v.w += bl[o + 3];
                __half2 h01 = __floats2half2_rn(v.x, v.y);
                __half2 h23 = __floats2half2_rn(v.z, v.w);
                unsigned long long pk = ((unsigned long long)h2_bits(h23) << 32)
                                        | (unsigned long long)h2_bits(h01);
                *(unsigned long long*)&g_xlh[node * 64 + o / 2] = pk;
            } else {
                const int o2 = o - 128;
                v.x += br[o2]; v.y += br[o2 + 1]; v.z += br[o2 + 2]; v.w += br[o2 + 3];
                *(float4*)&g_xr[node * 128 + o2] = v;
            }
        }
    }
}

// ---------------- fused GATv2 aggregation (one warp per dst node) ----------------
// max-free segment softmax (scores bounded small by construction); xl in fp16
// (half the L2 bytes). Round-3 structure: direct CSR index loads (L1-hit
// broadcast), 4 independent states, conditional 4-deep prefetch.
__device__ __forceinline__ void edge_update(const uint2 raw, const float4 xr4, const float4 at4,
                                            float& d, float4& acc) {
    float2 a01 = __half22float2(*(const __half2*)&raw.x);
    float2 a23 = __half22float2(*(const __half2*)&raw.y);
    float tx = a01.x + xr4.x; tx = fmaxf(tx, SLOPE * tx);
    float ty = a01.y + xr4.y; ty = fmaxf(ty, SLOPE * ty);
    float tz = a23.x + xr4.z; tz = fmaxf(tz, SLOPE * tz);
    float tw = a23.y + xr4.w; tw = fmaxf(tw, SLOPE * tw);
    float p = tx * at4.x + ty * at4.y + tz * at4.z + tw * at4.w;
    p += __shfl_xor_sync(0xffffffffu, p, 1);
    p += __shfl_xor_sync(0xffffffffu, p, 2);
    p += __shfl_xor_sync(0xffffffffu, p, 4);   // per-head score (8-lane groups)
    float w = __expf(p);
    d += w;
    acc.x = fmaf(w, a01.x, acc.x);
    acc.y = fmaf(w, a01.y, acc.y);
    acc.z = fmaf(w, a23.x, acc.z);
    acc.w = fmaf(w, a23.y, acc.w);
}

__global__ void gat_agg_kernel(const float* __restrict__ att, const float* __restrict__ bias) {
    const int warp = threadIdx.x >> 5;
    const int lane = threadIdx.x & 31;
    const int node = blockIdx.x * 8 + warp;

    const float4 xr4 = *(const float4*)(g_xr + node * 128 + lane * 4);
    const float4 at4 = *(const float4*)(att + lane * 4);
    const float4 b4  = *(const float4*)(bias + lane * 4);

    const int beg = g_rowptr[node];
    const int end = g_rowptr[node + 1];

    float d0 = 0.f, d1 = 0.f, d2 = 0.f, d3 = 0.f;
    float4 acc0 = make_float4(0.f, 0.f, 0.f, 0.f);
    float4 acc1 = acc0, acc2 = acc0, acc3 = acc0;

    uint2 r0 = make_uint2(0u, 0u);
    uint2 r1 = r0, r2 = r0, r3 = r0;
    if (beg     < end) r0 = *(const uint2*)(g_xlh + g_csr_src[beg]     * 64 + lane * 2);
    if (beg + 1 < end) r1 = *(const uint2*)(g_xlh + g_csr_src[beg + 1] * 64 + lane * 2);
    if (beg + 2 < end) r2 = *(const uint2*)(g_xlh + g_csr_src[beg + 2] * 64 + lane * 2);
    if (beg + 3 < end) r3 = *(const uint2*)(g_xlh + g_csr_src[beg + 3] * 64 + lane * 2);

    int k = beg;
    for (; k + 4 <= end; k += 4) {
        uint2 n0 = r0, n1 = r1, n2 = r2, n3 = r3;
        if (k + 4 < end) n0 = *(const uint2*)(g_xlh + g_csr_src[k + 4] * 64 + lane * 2);
        if (k + 5 < end) n1 = *(const uint2*)(g_xlh + g_csr_src[k + 5] * 64 + lane * 2);
        if (k + 6 < end) n2 = *(const uint2*)(g_xlh + g_csr_src[k + 6] * 64 + lane * 2);
        if (k + 7 < end) n3 = *(const uint2*)(g_xlh + g_csr_src[k + 7] * 64 + lane * 2);
        edge_update(r0, xr4, at4, d0, acc0);
        edge_update(r1, xr4, at4, d1, acc1);
        edge_update(r2, xr4, at4, d2, acc2);
        edge_update(r3, xr4, at4, d3, acc3);
        r0 = n0; r1 = n1; r2 = n2; r3 = n3;
    }
    if (k     < end) edge_update(r0, xr4, at4, d0, acc0);
    if (k + 1 < end) edge_update(r1, xr4, at4, d1, acc1);
    if (k + 2 < end) edge_update(r2, xr4, at4, d2, acc2);

    float dsum = (d0 + d1) + (d2 + d3);
    float4 acc;
    acc.x = (acc0.x + acc1.x) + (acc2.x + acc3.x);
    acc.y = (acc0.y + acc1.y) + (acc2.y + acc3.y);
    acc.z = (acc0.z + acc1.z) + (acc2.z + acc3.z);
    acc.w = (acc0.w + acc1.w) + (acc2.w + acc3.w);

    float inv = 1.f / (dsum + 1e-16f);
    float4 o;
    o.x = fmaxf(fmaf(acc.x, inv, b4.x), 0.f);
    o.y = fmaxf(fmaf(acc.y, inv, b4.y), 0.f);
    o.z = fmaxf(fmaf(acc.z, inv, b4.z), 0.f);
    o.w = fmaxf(fmaf(acc.w, inv, b4.w), 0.f);
    *(float4*)(g_h + node * 128 + lane * 4) = o;
}

// ---------------- global mean pool (batch is sorted) ----------------
__global__ void pool_kernel(const int* __restrict__ batch) {
    const int g = blockIdx.x;
    const int t = threadIdx.x;  // 128 threads
    __shared__ int sb, se;
    if (t == 0) {
        int lo = 0, hi = NN;
        while (lo < hi) { int mid = (lo + hi) >> 1; if (batch[mid] < g) lo = mid + 1; else hi = mid; }
        sb = lo;
        hi = NN;
        while (lo < hi) { int mid = (lo + hi) >> 1; if (batch[mid] < g + 1) lo = mid + 1; else hi = mid; }
        se = lo;
    }
    __syncthreads();
    float s0 = 0.f, s1 = 0.f, s2 = 0.f, s3 = 0.f;
    int n = sb;
    for (; n + 4 <= se; n += 4) {
        s0 += g_h[(n + 0) * 128 + t];
        s1 += g_h[(n + 1) * 128 + t];
        s2 += g_h[(n + 2) * 128 + t];
        s3 += g_h[(n + 3) * 128 + t];
    }
    for (; n < se; n++) s0 += g_h[n * 128 + t];
    float s = (s0 + s1) + (s2 + s3);
    int cnt = se - sb;
    g_pool[g * 128 + t] = s / (float)(cnt > 0 ? cnt : 1);
}

// ---------------- MLP head ----------------
__global__ void fc_bn_relu_kernel(int stage,
                                  const float* __restrict__ W, const float* __restrict__ b,
                                  const float* __restrict__ gamma, const float* __restrict__ beta) {
    const float* in = (stage == 0) ? g_pool : g_m1;
    float* out      = (stage == 0) ? g_m1   : g_m2;
    const int g = blockIdx.x, t = threadIdx.x;
    __shared__ float sin[128];
    sin[t] = in[g * 128 + t];
    __syncthreads();
    float a0 = b[t], a1 = 0.f;
#pragma unroll 4
    for (int k = 0; k < 128; k += 2) {
        a0 = fmaf(sin[k],     W[(k)     * 128 + t], a0);
        a1 = fmaf(sin[k + 1], W[(k + 1) * 128 + t], a1);
    }
    float a = a0 + a1;
    float scale = gamma[t] * rsqrtf(1.0f + 1e-5f);
    a = fmaxf(fmaf(a, scale, beta[t]), 0.f);
    out[g * 128 + t] = a;
}

__global__ void fc3_kernel(const float* __restrict__ W, const float* __restrict__ b,
                           float* __restrict__ out) {
    const int g = blockIdx.x, t = threadIdx.x;  // 128 threads
    __shared__ float sin[128];
    __shared__ float w0[4], w1[4];
    sin[t] = g_m2[g * 128 + t];
    __syncthreads();
    float p0 = sin[t] * W[t * 2 + 0];
    float p1 = sin[t] * W[t * 2 + 1];
#pragma unroll
    for (int off = 16; off; off >>= 1) {
        p0 += __shfl_xor_sync(0xffffffffu, p0, off);
        p1 += __shfl_xor_sync(0xffffffffu, p1, off);
    }
    if ((t & 31) == 0) { w0[t >> 5] = p0; w1[t >> 5] = p1; }
    __syncthreads();
    if (t == 0) out[g * 2 + 0] = w0[0] + w0[1] + w0[2] + w0[3] + b[0];
    if (t == 1) out[g * 2 + 1] = w1[0] + w1[1] + w1[2] + w1[3] + b[1];
}

// ---------------- launch ----------------
extern "C" void kernel_launch(void* const* d_in, const int* in_sizes, int n_in,
                              void* d_out, int out_size) {
    const float* x      = (const float*)d_in[0];
    const int*   ei     = (const int*)  d_in[1];
    const int*   batch  = (const int*)  d_in[2];
    const float* l1_Wl  = (const float*)d_in[3];
    const float* l1_bl  = (const float*)d_in[4];
    const float* l1_Wr  = (const float*)d_in[5];
    const float* l1_br  = (const float*)d_in[6];
    const float* l1_att = (const float*)d_in[7];
    const float* l1_bias= (const float*)d_in[8];
    const float* l2_Wl  = (const float*)d_in[9];
    const float* l2_bl  = (const float*)d_in[10];
    const float* l2_Wr  = (const float*)d_in[11];
    const float* l2_br  = (const float*)d_in[12];
    const float* l2_att = (const float*)d_in[13];
    const float* l2_bias= (const float*)d_in[14];
    const float* fc1_W  = (const float*)d_in[15];
    const float* fc1_b  = (const float*)d_in[16];
    const float* bn1_g  = (const float*)d_in[17];
    const float* bn1_b  = (const float*)d_in[18];
    const float* fc2_W  = (const float*)d_in[19];
    const float* fc2_b  = (const float*)d_in[20];
    const float* bn2_g  = (const float*)d_in[21];
    const float* bn2_b  = (const float*)d_in[22];
    const float* fc3_W  = (const float*)d_in[23];
    const float* fc3_b  = (const float*)d_in[24];

    const int* src = ei;
    const int* dst = ei + EE;
    float* out = (float*)d_out;

    // CSR by destination (shared by both layers)
    zero_deg_kernel<<<200, 256>>>();
    hist_kernel<<<1600, 256>>>(dst);
    scan_kernel<<<1, 1024>>>();
    scatter_kernel<<<1600, 256>>>(src, dst);

    // Layer 1
    dual_gemm_kernel<16><<<NN / 64, 256>>>(x, l1_Wl, l1_bl, l1_Wr, l1_br);
    gat_agg_kernel<<<NN / 8, 256>>>(l1_att, l1_bias);

    // Layer 2
    dual_gemm_kernel<128><<<NN / 64, 256>>>(nullptr, l2_Wl, l2_bl, l2_Wr, l2_br);
    gat_agg_kernel<<<NN / 8, 256>>>(l2_att, l2_bias);

    // Pool + MLP head
    pool_kernel<<<GG, 128>>>(batch);
    fc_bn_relu_kernel<<<GG, 128>>>(0, fc1_W, fc1_b, bn1_g, bn1_b);
    fc_bn_relu_kernel<<<GG, 128>>>(1, fc2_W, fc2_b, bn2_g, bn2_b);
    fc3_kernel<<<GG, 128>>>(fc3_W, fc3_b, out);
}